// round 6
// baseline (speedup 1.0000x reference)
#include <cuda_runtime.h>

// PrevEmbedding: out[b,t,:] = LN_src(gathered_row) + LN_emb(pos_emb[t] + type_emb[type])
// Key optimization: LN is per-row, so we LN only the 2048 gathered rows,
// never the full 32000x768 table.

#define HD   768
#define TPB  256   // 3 elements per thread
#define NW   (TPB / 32)
#define LN_EPS 1e-5f
#define MAX_BT 2048

__device__ int g_ids[MAX_BT];

// Decode prev_ids robustly whether the buffer is int64 or int32.
// If int64 (values nonneg < 2^31), the int32 view has zero high words at odd
// indices. Genuine int32 data has ~0 probability of 1024 zeros at odd slots.
__global__ void decode_ids_kernel(const int* __restrict__ raw, int BT) {
    __shared__ int odd_nonzero;
    if (threadIdx.x == 0) odd_nonzero = 0;
    __syncthreads();
    for (int i = threadIdx.x; i < BT; i += blockDim.x) {
        if ((i & 1) && raw[i] != 0) atomicOr(&odd_nonzero, 1);
    }
    __syncthreads();
    const bool is64 = (odd_nonzero == 0);
    for (int i = threadIdx.x; i < BT; i += blockDim.x) {
        // int64 path: low word of element i (nonneg ids fit in 32 bits)
        g_ids[i] = is64 ? raw[2 * i] : raw[i];
    }
}

__global__ __launch_bounds__(TPB)
void prev_embedding_kernel(
    const float* __restrict__ cv,        // [V, H]
    const float* __restrict__ ocr,       // [B, N, H]
    const float* __restrict__ cv_g,
    const float* __restrict__ cv_b,
    const float* __restrict__ ocr_g,
    const float* __restrict__ ocr_b,
    const float* __restrict__ pos_emb,   // [T, H]
    const float* __restrict__ type_emb,  // [2, H]
    const float* __restrict__ emb_g,
    const float* __restrict__ emb_b,
    float* __restrict__ out,             // [B, T, H]
    int V, int N, int T)
{
    const int bt = blockIdx.x;
    const int b  = bt / T;
    const int t  = bt - b * T;

    int id = g_ids[bt];

    const float* src;
    const float* gam;
    const float* bet;
    if (id >= V) {
        int oi = id - V;
        if (oi > N - 1) oi = N - 1;
        src = ocr + ((long long)b * N + oi) * HD;
        gam = ocr_g; bet = ocr_b;
    } else {
        int ci = id;
        if (ci < 0) ci = 0;
        if (ci > V - 1) ci = V - 1;
        src = cv + (long long)ci * HD;
        gam = cv_g; bet = cv_b;
    }

    const int type_id = (t >= V) ? 1 : 0;   // faithful to reference (always 0 here)
    const float* pe = pos_emb + t * HD;
    const float* te = type_emb + type_id * HD;

    float x[3], p[3];
    float sx = 0.f, sxx = 0.f, sp = 0.f, spp = 0.f;

    #pragma unroll
    for (int k = 0; k < 3; k++) {
        const int h = threadIdx.x + k * TPB;
        const float xv = src[h];
        const float pv = pe[h] + te[h];
        x[k] = xv; p[k] = pv;
        sx  += xv; sxx += xv * xv;
        sp  += pv; spp += pv * pv;
    }

    // warp reduction of 4 accumulators
    #pragma unroll
    for (int off = 16; off > 0; off >>= 1) {
        sx  += __shfl_xor_sync(0xFFFFFFFFu, sx,  off);
        sxx += __shfl_xor_sync(0xFFFFFFFFu, sxx, off);
        sp  += __shfl_xor_sync(0xFFFFFFFFu, sp,  off);
        spp += __shfl_xor_sync(0xFFFFFFFFu, spp, off);
    }

    __shared__ float sm[4][NW];
    const int wid = threadIdx.x >> 5;
    const int lid = threadIdx.x & 31;
    if (lid == 0) {
        sm[0][wid] = sx;  sm[1][wid] = sxx;
        sm[2][wid] = sp;  sm[3][wid] = spp;
    }
    __syncthreads();

    float tsx = 0.f, tsxx = 0.f, tsp = 0.f, tspp = 0.f;
    #pragma unroll
    for (int w = 0; w < NW; w++) {
        tsx  += sm[0][w];  tsxx += sm[1][w];
        tsp  += sm[2][w];  tspp += sm[3][w];
    }

    const float inv_h = 1.0f / (float)HD;
    const float mu_x  = tsx * inv_h;
    const float var_x = fmaxf(tsxx * inv_h - mu_x * mu_x, 0.f);
    const float rx    = rsqrtf(var_x + LN_EPS);
    const float mu_p  = tsp * inv_h;
    const float var_p = fmaxf(tspp * inv_h - mu_p * mu_p, 0.f);
    const float rp    = rsqrtf(var_p + LN_EPS);

    float* o = out + (long long)bt * HD;
    #pragma unroll
    for (int k = 0; k < 3; k++) {
        const int h = threadIdx.x + k * TPB;
        const float yx = (x[k] - mu_x) * rx * gam[h]   + bet[h];
        const float yp = (p[k] - mu_p) * rp * emb_g[h] + emb_b[h];
        o[h] = yx + yp;
    }
}

extern "C" void kernel_launch(void* const* d_in, const int* in_sizes, int n_in,
                              void* d_out, int out_size) {
    const float* cv       = (const float*)d_in[0];   // [V, H]
    const float* ocr      = (const float*)d_in[1];   // [B, N, H]
    const int*   ids_raw  = (const int*)d_in[2];     // [B, T] int32 or int64 (decoded)
    const float* cv_g     = (const float*)d_in[3];
    const float* cv_b     = (const float*)d_in[4];
    const float* ocr_g    = (const float*)d_in[5];
    const float* ocr_b    = (const float*)d_in[6];
    const float* pos_emb  = (const float*)d_in[7];   // [T, H]
    const float* type_emb = (const float*)d_in[8];   // [2, H]
    const float* emb_g    = (const float*)d_in[9];
    const float* emb_b    = (const float*)d_in[10];
    float* out = (float*)d_out;

    const int Hs = in_sizes[3];             // 768
    const int V  = in_sizes[0] / Hs;        // 32000
    const int T  = in_sizes[7] / Hs;        // 128
    const int BT = in_sizes[2];             // 2048 (element count either dtype)
    const int B  = BT / T;                  // 16
    const int N  = in_sizes[1] / (B * Hs);  // 50

    decode_ids_kernel<<<1, 1024>>>(ids_raw, BT);
    prev_embedding_kernel<<<BT, TPB>>>(cv, ocr, cv_g, cv_b, ocr_g, ocr_b,
                                       pos_emb, type_emb, emb_g, emb_b,
                                       out, V, N, T);
}